// round 1
// baseline (speedup 1.0000x reference)
#include <cuda_runtime.h>
#include <math.h>

#define NB      262144
#define TT      80
#define NSTEP   30
#define RPB     256        // rows (threads) per block
#define TILE_STRIDE 33     // 32 staged elements (48..79) + 1 pad
#define OUT_STRIDE  31     // 30 outputs + 1 pad
#define DTC     0.1f
#define SMEM_BYTES ((2 * RPB * TILE_STRIDE + RPB * OUT_STRIDE) * sizeof(float))

__global__ __launch_bounds__(RPB, 2)
void traj_kernel(const float* __restrict__ params,
                 const float* __restrict__ sv_v,
                 const float* __restrict__ hh,
                 const float* __restrict__ dvv,
                 const float* __restrict__ svY,
                 const float* __restrict__ lvY,
                 const float* __restrict__ lvv,
                 float* __restrict__ out)
{
    extern __shared__ float smem[];
    float* sY = smem;                          // [RPB][TILE_STRIDE]
    float* sV = smem + RPB * TILE_STRIDE;      // [RPB][TILE_STRIDE]
    float* sO = smem + 2 * RPB * TILE_STRIDE;  // [RPB][OUT_STRIDE]

    const int tid = threadIdx.x;
    const int r0  = blockIdx.x * RPB;

    // Cooperative, coalesced staging of lv_Y_seq1 / lv_v_seq1 elements 48..79.
    // byte offset = row*320 + 192 -> 16B aligned, 128B per row = 4 full sectors.
    #pragma unroll
    for (int k = 0; k < 8; ++k) {
        int idx = k * RPB + tid;
        int row = idx >> 3;      // 8 float4 quads per row
        int q   = idx & 7;
        size_t g = (size_t)(r0 + row) * TT + 48 + q * 4;
        float4 ya = *reinterpret_cast<const float4*>(lvY + g);
        float4 va = *reinterpret_cast<const float4*>(lvv + g);
        float* dy = sY + row * TILE_STRIDE + q * 4;
        float* dw = sV + row * TILE_STRIDE + q * 4;
        dy[0] = ya.x; dy[1] = ya.y; dy[2] = ya.z; dy[3] = ya.w;
        dw[0] = va.x; dw[1] = va.y; dw[2] = va.z; dw[3] = va.w;
    }

    // Per-row initial state at t=49 (1 sector per row per array; unavoidable).
    const size_t sbase = (size_t)(r0 + tid) * TT + 49;
    float v   = __ldg(sv_v + sbase);
    float gap = __ldg(hh   + sbase);
    float dvl = __ldg(dvv  + sbase);
    float y   = __ldg(svY  + sbase);

    // Params: broadcast loads, L1-resident.
    const float s0  = __ldg(params + 0);
    const float Thw = __ldg(params + 1);
    const float pa  = __ldg(params + 2);
    const float pb  = __ldg(params + 3);
    const float v0  = __ldg(params + 4);
    const float inv_c2 = 1.0f / (2.0f * sqrtf(pa * pb));
    const float inv_v0 = 1.0f / v0;

    __syncthreads();

    const float* myY = sY + tid * TILE_STRIDE + 2;  // element 50 = tile index 2
    const float* myV = sV + tid * TILE_STRIDE + 2;
    float* myO = sO + tid * OUT_STRIDE;

    #pragma unroll
    for (int i = 0; i < NSTEP; ++i) {
        // s_star = s0 + max(v*Thw + v*dv/(2*sqrt(a*b)), 0)  (NaN-propagating max)
        float t      = v * Thw + (v * dvl) * inv_c2;
        float relu   = !(t <= 0.0f) ? t : 0.0f;
        float s_star = s0 + relu;

        float rv  = v * inv_v0;
        float rv2 = rv * rv;
        float rs  = __fdividef(s_star, gap);
        float a_calc = pa * (1.0f - rv2 * rv2 - rs * rs);

        float v2  = v + a_calc * DTC;
        // where(v2 <= 0, -v/DT, a_calc); 1/0.1f rounds to exactly 10.0f
        float a_t = (v2 <= 0.0f) ? (-v * 10.0f) : a_calc;

        v   = v + a_t * DTC;
        dvl = v - myV[i];
        y   = y + v * DTC;
        gap = myY[i] - y;
        myO[i] = y;
    }

    __syncthreads();

    // Coalesced writeback: block writes RPB*NSTEP contiguous floats.
    const size_t obase = (size_t)r0 * NSTEP;
    #pragma unroll
    for (int k = 0; k < NSTEP; ++k) {
        int idx = k * RPB + tid;
        int row = idx / NSTEP;
        int col = idx - row * NSTEP;
        out[obase + idx] = sO[row * OUT_STRIDE + col];
    }
}

extern "C" void kernel_launch(void* const* d_in, const int* in_sizes, int n_in,
                              void* d_out, int out_size) {
    const float* params = (const float*)d_in[0];
    const float* sv_v1  = (const float*)d_in[1];
    const float* h1     = (const float*)d_in[2];
    const float* dv1    = (const float*)d_in[3];
    const float* sv_Y1  = (const float*)d_in[4];
    const float* lvY    = (const float*)d_in[5];
    const float* lvv    = (const float*)d_in[6];
    float* out = (float*)d_out;

    cudaFuncSetAttribute(traj_kernel,
                         cudaFuncAttributeMaxDynamicSharedMemorySize,
                         (int)SMEM_BYTES);
    traj_kernel<<<NB / RPB, RPB, SMEM_BYTES>>>(params, sv_v1, h1, dv1, sv_Y1,
                                               lvY, lvv, out);
}